// round 16
// baseline (speedup 1.0000x reference)
#include <cuda_runtime.h>
#include <math.h>

#define NB    1024
#define EMB   400
#define WW    20
#define FHW   18
#define FSZ   324
#define RN    96
#define RELF  864
#define NSET  6
#define NREL  500
#define EPSf  1e-5f

// ---------------- scratch ----------------------------------------------------
__device__ float d_rhat[(size_t)NB * RELF];
__device__ float d_rp[RELF * 5 * 2];                 // krstat partials
__device__ float d_sc[RELF], d_sf[RELF];
__device__ float d_part[NSET * NB * 2];
__device__ float d_PQ[(size_t)NSET * NB * 54];
__device__ float d_ab[NSET * 2];
__device__ float d_p2[576 * 128 * 2];
__device__ float d_ss[NSET * RN * 2];
__device__ float d_soft[(size_t)NSET * NB * FSZ];

struct EPtrs { const int* e[NSET]; };

// ---------------- helpers ----------------------------------------------------
__device__ __forceinline__ float warp_sum(float v) {
#pragma unroll
    for (int o = 16; o > 0; o >>= 1) v += __shfl_down_sync(0xffffffffu, v, o);
    return v;
}
__device__ __forceinline__ float warp_max(float v) {
#pragma unroll
    for (int o = 16; o > 0; o >>= 1) v = fmaxf(v, __shfl_down_sync(0xffffffffu, v, o));
    return v;
}
__device__ __forceinline__ float hsum16(float v) {
#pragma unroll
    for (int o = 8; o > 0; o >>= 1) v += __shfl_down_sync(0xffffffffu, v, o, 16);
    return v;
}
__device__ __forceinline__ unsigned long long pk2(float lo, float hi) {
    unsigned long long r;
    asm("mov.b64 %0,{%1,%2};" : "=l"(r) : "f"(lo), "f"(hi));
    return r;
}
__device__ __forceinline__ void upk2(unsigned long long v, float& lo, float& hi) {
    asm("mov.b64 {%0,%1},%2;" : "=f"(lo), "=f"(hi) : "l"(v));
}
__device__ __forceinline__ unsigned long long add2(unsigned long long a, unsigned long long b) {
    unsigned long long d;
    asm("add.rn.f32x2 %0,%1,%2;" : "=l"(d) : "l"(a), "l"(b));
    return d;
}
__device__ __forceinline__ unsigned long long fma2(unsigned long long a, unsigned long long b, unsigned long long c) {
    unsigned long long d;
    asm("fma.rn.f32x2 %0,%1,%2,%3;" : "=l"(d) : "l"(a), "l"(b), "l"(c));
    return d;
}

// ---------------- kfront1: fused kstats1 (blocks 0..383) + krstatA (384..403)
__global__ void __launch_bounds__(256) kfront1(EPtrs ep, const float* __restrict__ E,
                                               const int* __restrict__ r_idx,
                                               const float* __restrict__ R) {
    int bx = blockIdx.x;
    int t = threadIdx.x;

    if (bx >= 384) {
        __shared__ int   h[100];
        __shared__ float cf[100];
        int idx = bx - 384;
        int by  = idx >> 2;
        int fx  = idx & 3;
        int rel0 = by * 100;
        if (t < 100) h[t] = 0;
        __syncthreads();
        for (int i = t; i < NB; i += 256) {
            int rv = r_idx[i] - rel0;
            if (rv >= 0 && rv < 100) atomicAdd(&h[rv], 1);
        }
        __syncthreads();
        if (t < 100) cf[t] = (float)h[t];
        __syncthreads();
        int f = fx * 256 + t;
        if (f >= RELF) return;
        float s = 0.f, s2 = 0.f;
#pragma unroll 4
        for (int i = 0; i < 100; i++) {
            float v = R[(size_t)(rel0 + i) * RELF + f];
            float c = cf[i];
            s  = fmaf(c, v, s);
            s2 = fmaf(c * v, v, s2);
        }
        d_rp[(f * 5 + by) * 2 + 0] = s;
        d_rp[(f * 5 + by) * 2 + 1] = s2;
        return;
    }

    int wid = t >> 5, lane = t & 31;
    int g = lane >> 4, l16 = lane & 15;
    __shared__ float simg[16][400];
    int sid0 = bx * 16 + wid * 2;

#pragma unroll
    for (int ss = 0; ss < 2; ss++) {
        int sid2 = sid0 + ss;
        int set2 = sid2 >> 10, b2 = sid2 & 1023;
        int eid2 = ep.e[set2][b2];
        float s = 0.f, s2 = 0.f;
        for (int i = lane; i < EMB; i += 32) {
            float v = E[(size_t)eid2 * EMB + i];
            simg[wid * 2 + ss][i] = v;
            s += v; s2 += v * v;
        }
        s = warp_sum(s); s2 = warp_sum(s2);
        if (lane == 0) { d_part[sid2 * 2] = s; d_part[sid2 * 2 + 1] = s2; }
    }
    __syncwarp();

    int sid = sid0 + g;
    const float* img = simg[wid * 2 + g];
    float aP[9], aQ[45];
#pragma unroll
    for (int i = 0; i < 9; i++)  aP[i] = 0.f;
#pragma unroll
    for (int i = 0; i < 45; i++) aQ[i] = 0.f;

    int pos = l16, y = 0, x = l16;
    while (pos < FSZ) {
        const float* row0 = &img[y * WW + x];
        float p[9];
#pragma unroll
        for (int dy = 0; dy < 3; dy++)
#pragma unroll
            for (int dx = 0; dx < 3; dx++)
                p[dy * 3 + dx] = row0[dy * WW + dx];
        int q = 0;
#pragma unroll
        for (int k1 = 0; k1 < 9; k1++) {
            aP[k1] += p[k1];
#pragma unroll
            for (int k2 = k1; k2 < 9; k2++) { aQ[q] = fmaf(p[k1], p[k2], aQ[q]); q++; }
        }
        pos += 16; x += 16;
        if (x >= FHW) { x -= FHW; y += 1; }
    }
#pragma unroll
    for (int c = 0; c < 9; c++)  aP[c] = hsum16(aP[c]);
#pragma unroll
    for (int c = 0; c < 45; c++) aQ[c] = hsum16(aQ[c]);
    if (l16 == 0) {
        size_t base = (size_t)sid * 54;
#pragma unroll
        for (int c = 0; c < 9; c++)  d_PQ[base + c] = aP[c];
#pragma unroll
        for (int c = 0; c < 45; c++) d_PQ[base + 9 + c] = aQ[c];
    }
}

// ---------------- kfront2: fused krstatB (blocks 0..3) + kreduce0 (4..9) ----
__global__ void __launch_bounds__(256) kfront2(const float* __restrict__ g2,
                                               const float* __restrict__ b2,
                                               const float* __restrict__ g0,
                                               const float* __restrict__ b0) {
    int bx = blockIdx.x;
    int t = threadIdx.x;

    if (bx < 4) {
        int f = bx * 256 + t;
        if (f >= RELF) return;
        float s = 0.f, s2 = 0.f;
#pragma unroll
        for (int i = 0; i < 5; i++) {
            s  += d_rp[(f * 5 + i) * 2 + 0];
            s2 += d_rp[(f * 5 + i) * 2 + 1];
        }
        float m   = s * (1.f / NB);
        float var = s2 * (1.f / NB) - m * m;
        float sc  = rsqrtf(var + EPSf) * g2[f];
        d_sc[f] = sc;
        d_sf[f] = b2[f] - m * sc;
        return;
    }

    int set = bx - 4;
    float s = 0.f, s2 = 0.f;
    for (int b = t; b < NB; b += 256) {
        s  += d_part[(set * NB + b) * 2 + 0];
        s2 += d_part[(set * NB + b) * 2 + 1];
    }
    float ws = warp_sum(s), ws2 = warp_sum(s2);
    __shared__ float sh[8][2];
    int wid = t >> 5, lane = t & 31;
    if (lane == 0) { sh[wid][0] = ws; sh[wid][1] = ws2; }
    __syncthreads();
    if (t == 0) {
        float S = 0.f, S2 = 0.f;
#pragma unroll
        for (int w = 0; w < 8; w++) { S += sh[w][0]; S2 += sh[w][1]; }
        const float inv = 1.f / ((float)NB * EMB);
        float m   = S * inv;
        float var = S2 * inv - m * m;
        float a   = g0[0] * rsqrtf(var + EPSf);
        d_ab[set * 2 + 0] = a;
        d_ab[set * 2 + 1] = b0[0] - m * a;
    }
}

// ---------------- kstats2a (R13 proven): single load phase, rhat fused -------
__global__ void __launch_bounds__(576) kstats2a(const int* __restrict__ r_idx,
                                                const float* __restrict__ R) {
    __shared__ float s_rh[8][RELF];
    __shared__ float s_pq[8][NSET * 54];
    int t = threadIdx.x;
    int set = t / RN, r = t - set * RN;
    int b0 = blockIdx.x * 8;

    for (int i = t; i < 8 * RELF; i += 576) {
        int bi = i / RELF, j = i - bi * RELF;
        int b = b0 + bi;
        float v = fmaf(R[(size_t)r_idx[b] * RELF + j], d_sc[j], d_sf[j]);
        s_rh[bi][j] = v;
        d_rhat[(size_t)b * RELF + j] = v;
    }
    for (int i = t; i < 8 * NSET * 54; i += 576) {
        int bi = i / (NSET * 54), j = i - bi * (NSET * 54);
        int s_ = j / 54, k = j - s_ * 54;
        s_pq[bi][j] = d_PQ[((size_t)s_ * NB + (b0 + bi)) * 54 + k];
    }
    __syncthreads();

    float alpha = d_ab[set * 2 + 0], beta = d_ab[set * 2 + 1];
    float S1 = 0.f, S2 = 0.f;
#pragma unroll 2
    for (int bi = 0; bi < 8; bi++) {
        const float* pq = &s_pq[bi][set * 54];
        const float* rh = &s_rh[bi][r * 9];
        float rhv[9], Srh = 0.f, SrP = 0.f;
#pragma unroll
        for (int k = 0; k < 9; k++) {
            rhv[k] = rh[k];
            Srh += rhv[k];
            SrP += rhv[k] * pq[k];
        }
        float quad = 0.f;
        int q = 0;
#pragma unroll
        for (int k1 = 0; k1 < 9; k1++) {
            quad += rhv[k1] * rhv[k1] * pq[9 + q]; q++;
#pragma unroll
            for (int k2 = k1 + 1; k2 < 9; k2++) {
                quad += 2.f * rhv[k1] * rhv[k2] * pq[9 + q]; q++;
            }
        }
        float mC = alpha * SrP + (float)FSZ * beta * Srh;
        float x2 = alpha * alpha * quad
                 + 2.f * alpha * beta * Srh * SrP
                 + (float)FSZ * beta * beta * Srh * Srh;
        S1 += mC;
        S2 += x2;
    }
    d_p2[(t * 128 + blockIdx.x) * 2 + 0] = S1;
    d_p2[(t * 128 + blockIdx.x) * 2 + 1] = S2;
}

// ---------------- kstats2b (R13 proven) --------------------------------------
__global__ void kstats2b(const float* __restrict__ g1, const float* __restrict__ b1) {
    int c = blockIdx.x, t = threadIdx.x;
    int set = c / RN, r = c - set * RN;
    float v1 = d_p2[(c * 128 + t) * 2 + 0];
    float v2 = d_p2[(c * 128 + t) * 2 + 1];
    float w1 = warp_sum(v1), w2 = warp_sum(v2);
    __shared__ float sh[4][2];
    int wid = t >> 5, lane = t & 31;
    if (lane == 0) { sh[wid][0] = w1; sh[wid][1] = w2; }
    __syncthreads();
    if (t == 0) {
        float A = sh[0][0] + sh[1][0] + sh[2][0] + sh[3][0];
        float B = sh[0][1] + sh[1][1] + sh[2][1] + sh[3][1];
        const float inv = 1.f / ((float)NB * FSZ);
        float m   = A * inv;
        float var = B * inv - m * m;
        float sc  = g1[r] * rsqrtf(var + EPSf);
        d_ss[(set * RN + r) * 2 + 0] = sc;
        d_ss[(set * RN + r) * 2 + 1] = b1[r] - m * sc;
    }
}

// ---------------- kmain v5: 6 warps, 1 pair/lane, full channel sweep ---------
// grid = (1024, 6), 192 threads. Warp w owns positions [54w, 54w+54);
// lanes 0..26 hold one packed position pair; each warp walks all 96 channels,
// so the channel sum completes per-lane (no cross-warp reduction).
#define TKM 192
__global__ void __launch_bounds__(TKM) kmain(EPtrs ep, const float* __restrict__ E) {
    int set = blockIdx.y, b = blockIdx.x, t = threadIdx.x;
    int wid = t >> 5, lane = t & 31;
    __shared__ float img[EMB];
    __shared__ __align__(16) float2 rw[RN * 10];   // 9 {sc*w} pairs + {sh} pair per ch
    __shared__ float ssc[RN];
    __shared__ float swm[6], sws[6];
    __shared__ float sbm, sbs;

    int eid = ep.e[set][b];
    float alpha = d_ab[set * 2 + 0], beta = d_ab[set * 2 + 1];

    // phase A: raw weights + scales + normalized image
    float vreg[5];
#pragma unroll
    for (int j = 0; j < 5; j++) {
        int i = t + j * TKM;
        vreg[j] = (i < RELF) ? d_rhat[(size_t)b * RELF + i] : 0.f;
    }
    float mysh = 0.f;
    if (t < RN) {
        ssc[t] = d_ss[(set * RN + t) * 2 + 0];
        mysh   = d_ss[(set * RN + t) * 2 + 1];
    }
    for (int i = t; i < EMB; i += TKM)
        img[i] = fmaf(E[(size_t)eid * EMB + i], alpha, beta);
    __syncthreads();

    // phase B: scale-folded duplicated weight pairs
#pragma unroll
    for (int j = 0; j < 5; j++) {
        int i = t + j * TKM;
        if (i < RELF) {
            int r = i / 9, k = i - r * 9;
            float w = vreg[j] * ssc[r];
            rw[r * 10 + k] = make_float2(w, w);
        }
    }
    if (t < RN) rw[t * 10 + 9] = make_float2(mysh, mysh);
    __syncthreads();

    // phase C: one packed position pair per lane
    int l = (lane < 27) ? lane : 26;
    int p0 = wid * 54 + 2 * l, p1 = p0 + 1;
    int y0 = p0 / FHW, x0 = p0 - y0 * FHW;
    int y1 = p1 / FHW, x1 = p1 - y1 * FHW;
    unsigned long long P[9];
#pragma unroll
    for (int dy = 0; dy < 3; dy++)
#pragma unroll
        for (int dx = 0; dx < 3; dx++)
            P[dy * 3 + dx] = pk2(img[(y0 + dy) * WW + x0 + dx],
                                 img[(y1 + dy) * WW + x1 + dx]);

    const unsigned long long ABSM = 0x7fffffff7fffffffULL;
    unsigned long long S = 0ull;
    const ulonglong2* rwq = (const ulonglong2*)rw;   // 5 x 16B per channel
#pragma unroll 4
    for (int r = 0; r < RN; r++) {
        ulonglong2 q0 = rwq[r * 5 + 0];
        ulonglong2 q1 = rwq[r * 5 + 1];
        ulonglong2 q2 = rwq[r * 5 + 2];
        ulonglong2 q3 = rwq[r * 5 + 3];
        ulonglong2 q4 = rwq[r * 5 + 4];              // w8, shift
        unsigned long long a = fma2(P[0], q0.x, q4.y);
        a = fma2(P[1], q0.y, a);  a = fma2(P[2], q1.x, a);
        a = fma2(P[3], q1.y, a);  a = fma2(P[4], q2.x, a);
        a = fma2(P[5], q2.y, a);  a = fma2(P[6], q3.x, a);
        a = fma2(P[7], q3.y, a);  a = fma2(P[8], q4.x, a);
        S = add2(S, add2(a, a & ABSM));              // += y + |y| = 2*relu(y)
    }
    float v0, v1;
    upk2(S, v0, v1);
    v0 *= 0.5f; v1 *= 0.5f;

    // block softmax over 324 positions (6 warps x 27 lanes x 2)
    bool act = lane < 27;
    const float NEGINF = __int_as_float(0xff800000u);
    float lm = act ? fmaxf(v0, v1) : NEGINF;
    lm = warp_max(lm);
    if (lane == 0) swm[wid] = lm;
    __syncthreads();
    if (t == 0) {
        float m = swm[0];
#pragma unroll
        for (int w = 1; w < 6; w++) m = fmaxf(m, swm[w]);
        sbm = m;
    }
    __syncthreads();
    float bm = sbm;
    float e0 = 0.f, e1 = 0.f;
    if (act) { e0 = __expf(v0 - bm); e1 = __expf(v1 - bm); }
    float ls = warp_sum(e0 + e1);
    if (lane == 0) sws[wid] = ls;
    __syncthreads();
    if (t == 0) {
        float s = 0.f;
#pragma unroll
        for (int w = 0; w < 6; w++) s += sws[w];
        sbs = s;
    }
    __syncthreads();
    if (act) {
        float2 o;
        if (eid == 0) {
            const float u = 1.f / (float)FSZ;
            o = make_float2(u, u);
        } else {
            float inv = 1.f / sbs;
            o = make_float2(e0 * inv, e1 * inv);
        }
        *(float2*)&d_soft[((size_t)set * NB + b) * FSZ + p0] = o;
    }
}

// ---------------- kfinal v2: float4 products ---------------------------------
__global__ void __launch_bounds__(96) kfinal(const float* __restrict__ p,
                                             float* __restrict__ out) {
    int b = blockIdx.x, t = threadIdx.x;
    float acc = 0.f;
    if (t < 81) {
        float4 pr = *(const float4*)&d_soft[((size_t)0 * NB + b) * FSZ + 4 * t];
#pragma unroll
        for (int s = 1; s < NSET; s++) {
            float4 v = *(const float4*)&d_soft[((size_t)s * NB + b) * FSZ + 4 * t];
            pr.x *= v.x; pr.y *= v.y; pr.z *= v.z; pr.w *= v.w;
        }
        float4 pv = *(const float4*)&p[4 * t];
        acc = fmaf(pr.x, pv.x, fmaf(pr.y, pv.y, fmaf(pr.z, pv.z, pr.w * pv.w)));
    }
    float ws = warp_sum(acc);
    __shared__ float sw[3];
    if ((t & 31) == 0) sw[t >> 5] = ws;
    __syncthreads();
    if (t == 0) out[b] = sw[0] + sw[1] + sw[2];
}

// ---------------- launcher (single stream, 6 launches) -----------------------
extern "C" void kernel_launch(void* const* d_in, const int* in_sizes, int n_in,
                              void* d_out, int out_size) {
    const int* r_idx = (const int*)d_in[0];
    EPtrs ep;
    for (int i = 0; i < NSET; i++) ep.e[i] = (const int*)d_in[1 + i];
    const float* E  = (const float*)d_in[7];
    const float* R  = (const float*)d_in[8];
    const float* g0 = (const float*)d_in[9];
    const float* b0 = (const float*)d_in[10];
    const float* g1 = (const float*)d_in[11];
    const float* b1 = (const float*)d_in[12];
    const float* g2 = (const float*)d_in[13];
    const float* b2 = (const float*)d_in[14];
    const float* p  = (const float*)d_in[15];
    float* out = (float*)d_out;

    kfront1 <<<404, 256>>>(ep, E, r_idx, R);
    kfront2 <<<10, 256>>>(g2, b2, g0, b0);
    kstats2a<<<128, 576>>>(r_idx, R);
    kstats2b<<<576, 128>>>(g1, b1);
    kmain   <<<dim3(NB, NSET), TKM>>>(ep, E);
    kfinal  <<<NB, 96>>>(p, out);
}

// round 17
// speedup vs baseline: 1.1857x; 1.1857x over previous
#include <cuda_runtime.h>
#include <math.h>

#define NB    1024
#define EMB   400
#define WW    20
#define FHW   18
#define FSZ   324
#define RN    96
#define RELF  864
#define NSET  6
#define NREL  500
#define EPSf  1e-5f

// ---------------- scratch ----------------------------------------------------
__device__ float d_rhat[(size_t)NB * RELF];
__device__ float d_rp[RELF * 5 * 2];                 // krstat partials
__device__ float d_sc[RELF], d_sf[RELF];
__device__ float d_part[NSET * NB * 2];
__device__ float d_PQ[(size_t)NSET * NB * 54];
__device__ float d_ab[NSET * 2];
__device__ float d_p2[576 * 128 * 2];
__device__ float d_ss[NSET * RN * 2];
__device__ float d_soft[(size_t)NSET * NB * FSZ];

struct EPtrs { const int* e[NSET]; };

// ---------------- helpers ----------------------------------------------------
__device__ __forceinline__ float warp_sum(float v) {
#pragma unroll
    for (int o = 16; o > 0; o >>= 1) v += __shfl_down_sync(0xffffffffu, v, o);
    return v;
}
__device__ __forceinline__ float warp_max(float v) {
#pragma unroll
    for (int o = 16; o > 0; o >>= 1) v = fmaxf(v, __shfl_down_sync(0xffffffffu, v, o));
    return v;
}
__device__ __forceinline__ float hsum16(float v) {
#pragma unroll
    for (int o = 8; o > 0; o >>= 1) v += __shfl_down_sync(0xffffffffu, v, o, 16);
    return v;
}
__device__ __forceinline__ unsigned long long pk2(float lo, float hi) {
    unsigned long long r;
    asm("mov.b64 %0,{%1,%2};" : "=l"(r) : "f"(lo), "f"(hi));
    return r;
}
__device__ __forceinline__ void upk2(unsigned long long v, float& lo, float& hi) {
    asm("mov.b64 {%0,%1},%2;" : "=f"(lo), "=f"(hi) : "l"(v));
}
__device__ __forceinline__ unsigned long long add2(unsigned long long a, unsigned long long b) {
    unsigned long long d;
    asm("add.rn.f32x2 %0,%1,%2;" : "=l"(d) : "l"(a), "l"(b));
    return d;
}
__device__ __forceinline__ unsigned long long fma2(unsigned long long a, unsigned long long b, unsigned long long c) {
    unsigned long long d;
    asm("fma.rn.f32x2 %0,%1,%2,%3;" : "=l"(d) : "l"(a), "l"(b), "l"(c));
    return d;
}

// ---------------- kfront1: fused kstats1 (blocks 0..383) + krstatA (384..403)
__global__ void __launch_bounds__(256) kfront1(EPtrs ep, const float* __restrict__ E,
                                               const int* __restrict__ r_idx,
                                               const float* __restrict__ R) {
    int bx = blockIdx.x;
    int t = threadIdx.x;

    if (bx >= 384) {
        __shared__ int   h[100];
        __shared__ float cf[100];
        int idx = bx - 384;
        int by  = idx >> 2;
        int fx  = idx & 3;
        int rel0 = by * 100;
        if (t < 100) h[t] = 0;
        __syncthreads();
        for (int i = t; i < NB; i += 256) {
            int rv = r_idx[i] - rel0;
            if (rv >= 0 && rv < 100) atomicAdd(&h[rv], 1);
        }
        __syncthreads();
        if (t < 100) cf[t] = (float)h[t];
        __syncthreads();
        int f = fx * 256 + t;
        if (f >= RELF) return;
        float s = 0.f, s2 = 0.f;
#pragma unroll 4
        for (int i = 0; i < 100; i++) {
            float v = R[(size_t)(rel0 + i) * RELF + f];
            float c = cf[i];
            s  = fmaf(c, v, s);
            s2 = fmaf(c * v, v, s2);
        }
        d_rp[(f * 5 + by) * 2 + 0] = s;
        d_rp[(f * 5 + by) * 2 + 1] = s2;
        return;
    }

    int wid = t >> 5, lane = t & 31;
    int g = lane >> 4, l16 = lane & 15;
    __shared__ float simg[16][400];
    int sid0 = bx * 16 + wid * 2;

#pragma unroll
    for (int ss = 0; ss < 2; ss++) {
        int sid2 = sid0 + ss;
        int set2 = sid2 >> 10, b2 = sid2 & 1023;
        int eid2 = ep.e[set2][b2];
        float s = 0.f, s2 = 0.f;
        for (int i = lane; i < EMB; i += 32) {
            float v = E[(size_t)eid2 * EMB + i];
            simg[wid * 2 + ss][i] = v;
            s += v; s2 += v * v;
        }
        s = warp_sum(s); s2 = warp_sum(s2);
        if (lane == 0) { d_part[sid2 * 2] = s; d_part[sid2 * 2 + 1] = s2; }
    }
    __syncwarp();

    int sid = sid0 + g;
    const float* img = simg[wid * 2 + g];
    float aP[9], aQ[45];
#pragma unroll
    for (int i = 0; i < 9; i++)  aP[i] = 0.f;
#pragma unroll
    for (int i = 0; i < 45; i++) aQ[i] = 0.f;

    int pos = l16, y = 0, x = l16;
    while (pos < FSZ) {
        const float* row0 = &img[y * WW + x];
        float p[9];
#pragma unroll
        for (int dy = 0; dy < 3; dy++)
#pragma unroll
            for (int dx = 0; dx < 3; dx++)
                p[dy * 3 + dx] = row0[dy * WW + dx];
        int q = 0;
#pragma unroll
        for (int k1 = 0; k1 < 9; k1++) {
            aP[k1] += p[k1];
#pragma unroll
            for (int k2 = k1; k2 < 9; k2++) { aQ[q] = fmaf(p[k1], p[k2], aQ[q]); q++; }
        }
        pos += 16; x += 16;
        if (x >= FHW) { x -= FHW; y += 1; }
    }
#pragma unroll
    for (int c = 0; c < 9; c++)  aP[c] = hsum16(aP[c]);
#pragma unroll
    for (int c = 0; c < 45; c++) aQ[c] = hsum16(aQ[c]);
    if (l16 == 0) {
        size_t base = (size_t)sid * 54;
#pragma unroll
        for (int c = 0; c < 9; c++)  d_PQ[base + c] = aP[c];
#pragma unroll
        for (int c = 0; c < 45; c++) d_PQ[base + 9 + c] = aQ[c];
    }
}

// ---------------- kfront2: fused krstatB (blocks 0..3) + kreduce0 (4..9) ----
__global__ void __launch_bounds__(256) kfront2(const float* __restrict__ g2,
                                               const float* __restrict__ b2,
                                               const float* __restrict__ g0,
                                               const float* __restrict__ b0) {
    int bx = blockIdx.x;
    int t = threadIdx.x;

    if (bx < 4) {
        int f = bx * 256 + t;
        if (f >= RELF) return;
        float s = 0.f, s2 = 0.f;
#pragma unroll
        for (int i = 0; i < 5; i++) {
            s  += d_rp[(f * 5 + i) * 2 + 0];
            s2 += d_rp[(f * 5 + i) * 2 + 1];
        }
        float m   = s * (1.f / NB);
        float var = s2 * (1.f / NB) - m * m;
        float sc  = rsqrtf(var + EPSf) * g2[f];
        d_sc[f] = sc;
        d_sf[f] = b2[f] - m * sc;
        return;
    }

    int set = bx - 4;
    float s = 0.f, s2 = 0.f;
    for (int b = t; b < NB; b += 256) {
        s  += d_part[(set * NB + b) * 2 + 0];
        s2 += d_part[(set * NB + b) * 2 + 1];
    }
    float ws = warp_sum(s), ws2 = warp_sum(s2);
    __shared__ float sh[8][2];
    int wid = t >> 5, lane = t & 31;
    if (lane == 0) { sh[wid][0] = ws; sh[wid][1] = ws2; }
    __syncthreads();
    if (t == 0) {
        float S = 0.f, S2 = 0.f;
#pragma unroll
        for (int w = 0; w < 8; w++) { S += sh[w][0]; S2 += sh[w][1]; }
        const float inv = 1.f / ((float)NB * EMB);
        float m   = S * inv;
        float var = S2 * inv - m * m;
        float a   = g0[0] * rsqrtf(var + EPSf);
        d_ab[set * 2 + 0] = a;
        d_ab[set * 2 + 1] = b0[0] - m * a;
    }
}

// ---------------- kstats2a (proven): single load phase, rhat fused -----------
__global__ void __launch_bounds__(576) kstats2a(const int* __restrict__ r_idx,
                                                const float* __restrict__ R) {
    __shared__ float s_rh[8][RELF];
    __shared__ float s_pq[8][NSET * 54];
    int t = threadIdx.x;
    int set = t / RN, r = t - set * RN;
    int b0 = blockIdx.x * 8;

    for (int i = t; i < 8 * RELF; i += 576) {
        int bi = i / RELF, j = i - bi * RELF;
        int b = b0 + bi;
        float v = fmaf(R[(size_t)r_idx[b] * RELF + j], d_sc[j], d_sf[j]);
        s_rh[bi][j] = v;
        d_rhat[(size_t)b * RELF + j] = v;
    }
    for (int i = t; i < 8 * NSET * 54; i += 576) {
        int bi = i / (NSET * 54), j = i - bi * (NSET * 54);
        int s_ = j / 54, k = j - s_ * 54;
        s_pq[bi][j] = d_PQ[((size_t)s_ * NB + (b0 + bi)) * 54 + k];
    }
    __syncthreads();

    float alpha = d_ab[set * 2 + 0], beta = d_ab[set * 2 + 1];
    float S1 = 0.f, S2 = 0.f;
#pragma unroll 2
    for (int bi = 0; bi < 8; bi++) {
        const float* pq = &s_pq[bi][set * 54];
        const float* rh = &s_rh[bi][r * 9];
        float rhv[9], Srh = 0.f, SrP = 0.f;
#pragma unroll
        for (int k = 0; k < 9; k++) {
            rhv[k] = rh[k];
            Srh += rhv[k];
            SrP += rhv[k] * pq[k];
        }
        float quad = 0.f;
        int q = 0;
#pragma unroll
        for (int k1 = 0; k1 < 9; k1++) {
            quad += rhv[k1] * rhv[k1] * pq[9 + q]; q++;
#pragma unroll
            for (int k2 = k1 + 1; k2 < 9; k2++) {
                quad += 2.f * rhv[k1] * rhv[k2] * pq[9 + q]; q++;
            }
        }
        float mC = alpha * SrP + (float)FSZ * beta * Srh;
        float x2 = alpha * alpha * quad
                 + 2.f * alpha * beta * Srh * SrP
                 + (float)FSZ * beta * beta * Srh * Srh;
        S1 += mC;
        S2 += x2;
    }
    d_p2[(t * 128 + blockIdx.x) * 2 + 0] = S1;
    d_p2[(t * 128 + blockIdx.x) * 2 + 1] = S2;
}

// ---------------- kstats2b (proven) ------------------------------------------
__global__ void kstats2b(const float* __restrict__ g1, const float* __restrict__ b1) {
    int c = blockIdx.x, t = threadIdx.x;
    int set = c / RN, r = c - set * RN;
    float v1 = d_p2[(c * 128 + t) * 2 + 0];
    float v2 = d_p2[(c * 128 + t) * 2 + 1];
    float w1 = warp_sum(v1), w2 = warp_sum(v2);
    __shared__ float sh[4][2];
    int wid = t >> 5, lane = t & 31;
    if (lane == 0) { sh[wid][0] = w1; sh[wid][1] = w2; }
    __syncthreads();
    if (t == 0) {
        float A = sh[0][0] + sh[1][0] + sh[2][0] + sh[3][0];
        float B = sh[0][1] + sh[1][1] + sh[2][1] + sh[3][1];
        const float inv = 1.f / ((float)NB * FSZ);
        float m   = A * inv;
        float var = B * inv - m * m;
        float sc  = g1[r] * rsqrtf(var + EPSf);
        d_ss[(set * RN + r) * 2 + 0] = sc;
        d_ss[(set * RN + r) * 2 + 1] = b1[r] - m * sc;
    }
}

// ---------------- kmain v6: 4 warps, 2 ch-groups x 2 pos-groups, 3 packs/lane
// grid = (1024, 6), 128 threads. chg = wid&1 (48 channels), pg = wid>>1
// (162 positions); lanes 0..26 hold 3 packed position pairs.
#define TKM 128
__global__ void __launch_bounds__(TKM) kmain(EPtrs ep, const float* __restrict__ E) {
    int set = blockIdx.y, b = blockIdx.x, t = threadIdx.x;
    int wid = t >> 5, lane = t & 31;
    int chg = wid & 1, pg = wid >> 1;
    __shared__ float img[EMB];
    __shared__ __align__(16) float2 rw[RN * 10];
    __shared__ float ssc[RN];
    __shared__ __align__(16) float2 red[4][27][3];
    __shared__ float smax[2], ssum[2];

    int eid = ep.e[set][b];
    float alpha = d_ab[set * 2 + 0], beta = d_ab[set * 2 + 1];

    // phase A: raw weights + scales + normalized image
    float vreg[7];
#pragma unroll
    for (int j = 0; j < 7; j++) {
        int i = t + j * TKM;
        vreg[j] = (i < RELF) ? d_rhat[(size_t)b * RELF + i] : 0.f;
    }
    float mysh = 0.f;
    if (t < RN) {
        ssc[t] = d_ss[(set * RN + t) * 2 + 0];
        mysh   = d_ss[(set * RN + t) * 2 + 1];
    }
    for (int i = t; i < EMB; i += TKM)
        img[i] = fmaf(E[(size_t)eid * EMB + i], alpha, beta);
    __syncthreads();

    // phase B: scale-folded duplicated weight pairs
#pragma unroll
    for (int j = 0; j < 7; j++) {
        int i = t + j * TKM;
        if (i < RELF) {
            int r = i / 9, k = i - r * 9;
            float w = vreg[j] * ssc[r];
            rw[r * 10 + k] = make_float2(w, w);
        }
    }
    if (t < RN) rw[t * 10 + 9] = make_float2(mysh, mysh);
    __syncthreads();

    // phase C: 3 packed pairs (6 consecutive positions) per lane
    int l = (lane < 27) ? lane : 26;
    int pbase = pg * 162 + 6 * l;
    unsigned long long P[3][9];
#pragma unroll
    for (int j = 0; j < 3; j++) {
        int p0 = pbase + 2 * j, p1 = p0 + 1;
        int y0 = p0 / FHW, x0 = p0 - y0 * FHW;
        int y1 = p1 / FHW, x1 = p1 - y1 * FHW;
#pragma unroll
        for (int dy = 0; dy < 3; dy++)
#pragma unroll
            for (int dx = 0; dx < 3; dx++)
                P[j][dy * 3 + dx] = pk2(img[(y0 + dy) * WW + x0 + dx],
                                        img[(y1 + dy) * WW + x1 + dx]);
    }

    const unsigned long long ABSM = 0x7fffffff7fffffffULL;
    unsigned long long S[3];
#pragma unroll
    for (int j = 0; j < 3; j++) S[j] = 0ull;
    const ulonglong2* rwq = (const ulonglong2*)rw;   // 5 x 16B per channel
    int r0 = chg * 48;
#pragma unroll 4
    for (int rr = 0; rr < 48; rr++) {
        int r = r0 + rr;
        ulonglong2 q0 = rwq[r * 5 + 0];
        ulonglong2 q1 = rwq[r * 5 + 1];
        ulonglong2 q2 = rwq[r * 5 + 2];
        ulonglong2 q3 = rwq[r * 5 + 3];
        ulonglong2 q4 = rwq[r * 5 + 4];              // w8, shift
#pragma unroll
        for (int j = 0; j < 3; j++) {
            unsigned long long a = fma2(P[j][0], q0.x, q4.y);
            a = fma2(P[j][1], q0.y, a);  a = fma2(P[j][2], q1.x, a);
            a = fma2(P[j][3], q1.y, a);  a = fma2(P[j][4], q2.x, a);
            a = fma2(P[j][5], q2.y, a);  a = fma2(P[j][6], q3.x, a);
            a = fma2(P[j][7], q3.y, a);  a = fma2(P[j][8], q4.x, a);
            S[j] = add2(S[j], add2(a, a & ABSM));    // += y + |y| = 2*relu(y)
        }
    }
    if (lane < 27) {
#pragma unroll
        for (int j = 0; j < 3; j++) {
            float lo, hi; upk2(S[j], lo, hi);
            red[wid][lane][j] = make_float2(lo, hi);
        }
    }
    __syncthreads();

    // reduction + softmax: warp 0 -> pg0 (red[0]+red[1]); warp 1 -> pg1 (red[2]+red[3])
    bool redw = (wid < 2);
    bool act = redw && (lane < 27);
    float v[6];
    const float NEGINF = __int_as_float(0xff800000u);
    float lm = NEGINF;
    if (redw) {
        int ll = (lane < 27) ? lane : 26;
#pragma unroll
        for (int j = 0; j < 3; j++) {
            float2 a0 = red[wid * 2 + 0][ll][j];
            float2 a1 = red[wid * 2 + 1][ll][j];
            v[2 * j]     = 0.5f * (a0.x + a1.x);
            v[2 * j + 1] = 0.5f * (a0.y + a1.y);
        }
        if (act) {
#pragma unroll
            for (int j = 0; j < 6; j++) lm = fmaxf(lm, v[j]);
        }
        lm = warp_max(lm);
        if (lane == 0) smax[wid] = lm;
    }
    __syncthreads();
    float bm = fmaxf(smax[0], smax[1]);
    float e[6], ls = 0.f;
    if (redw) {
        if (act) {
#pragma unroll
            for (int j = 0; j < 6; j++) { e[j] = __expf(v[j] - bm); ls += e[j]; }
        }
        ls = warp_sum(ls);
        if (lane == 0) ssum[wid] = ls;
    }
    __syncthreads();
    if (act) {
        float tot = ssum[0] + ssum[1];
        float* dst = &d_soft[((size_t)set * NB + b) * FSZ + wid * 162 + 6 * lane];
        if (eid == 0) {
            const float u = 1.f / (float)FSZ;
#pragma unroll
            for (int j = 0; j < 3; j++)
                *(float2*)&dst[2 * j] = make_float2(u, u);
        } else {
            float inv = 1.f / tot;
#pragma unroll
            for (int j = 0; j < 3; j++)
                *(float2*)&dst[2 * j] = make_float2(e[2 * j] * inv, e[2 * j + 1] * inv);
        }
    }
}

// ---------------- kfinal v2: float4 products ---------------------------------
__global__ void __launch_bounds__(96) kfinal(const float* __restrict__ p,
                                             float* __restrict__ out) {
    int b = blockIdx.x, t = threadIdx.x;
    float acc = 0.f;
    if (t < 81) {
        float4 pr = *(const float4*)&d_soft[((size_t)0 * NB + b) * FSZ + 4 * t];
#pragma unroll
        for (int s = 1; s < NSET; s++) {
            float4 v = *(const float4*)&d_soft[((size_t)s * NB + b) * FSZ + 4 * t];
            pr.x *= v.x; pr.y *= v.y; pr.z *= v.z; pr.w *= v.w;
        }
        float4 pv = *(const float4*)&p[4 * t];
        acc = fmaf(pr.x, pv.x, fmaf(pr.y, pv.y, fmaf(pr.z, pv.z, pr.w * pv.w)));
    }
    float ws = warp_sum(acc);
    __shared__ float sw[3];
    if ((t & 31) == 0) sw[t >> 5] = ws;
    __syncthreads();
    if (t == 0) out[b] = sw[0] + sw[1] + sw[2];
}

// ---------------- launcher (single stream, 6 launches) -----------------------
extern "C" void kernel_launch(void* const* d_in, const int* in_sizes, int n_in,
                              void* d_out, int out_size) {
    const int* r_idx = (const int*)d_in[0];
    EPtrs ep;
    for (int i = 0; i < NSET; i++) ep.e[i] = (const int*)d_in[1 + i];
    const float* E  = (const float*)d_in[7];
    const float* R  = (const float*)d_in[8];
    const float* g0 = (const float*)d_in[9];
    const float* b0 = (const float*)d_in[10];
    const float* g1 = (const float*)d_in[11];
    const float* b1 = (const float*)d_in[12];
    const float* g2 = (const float*)d_in[13];
    const float* b2 = (const float*)d_in[14];
    const float* p  = (const float*)d_in[15];
    float* out = (float*)d_out;

    kfront1 <<<404, 256>>>(ep, E, r_idx, R);
    kfront2 <<<10, 256>>>(g2, b2, g0, b0);
    kstats2a<<<128, 576>>>(r_idx, R);
    kstats2b<<<576, 128>>>(g1, b1);
    kmain   <<<dim3(NB, NSET), TKM>>>(ep, E);
    kfinal  <<<NB, 96>>>(p, out);
}